// round 1
// baseline (speedup 1.0000x reference)
#include <cuda_runtime.h>
#include <cuda_bf16.h>

// Problem constants (fixed by the dataset)
#define N_NODES_MAX 50000
#define N_EDGES_MAX 800000
#define IN_FEATS    128
#define NUM_HEADS   4
#define OUT_FEATS   32
#define HD          (NUM_HEADS * OUT_FEATS)   // 128

// Scratch (static __device__ arrays; no allocation allowed)
__device__ float g_ft[N_NODES_MAX * HD];          // projected features [N,128]
__device__ float g_e [N_EDGES_MAX * NUM_HEADS];   // exp(scores) per edge/head
__device__ float g_s [N_NODES_MAX * NUM_HEADS];   // per-dst softmax denominators

// ---------------------------------------------------------------------------
// K0: zero the softmax denominators
// ---------------------------------------------------------------------------
__global__ void zero_s_kernel(int n) {
    int i = blockIdx.x * blockDim.x + threadIdx.x;
    if (i < n) g_s[i] = 0.0f;
}

// ---------------------------------------------------------------------------
// K1: ft[n][o] = sum_k feat[n][k] * W[o][k]
// Tiled SGEMM: BM=32 rows, BN=128 cols (all), BK=32. 256 threads, 4x4 microtile.
// Shared tiles stored k-major so compute reads are LDS.128 conflict-free /
// broadcast.
// ---------------------------------------------------------------------------
#define BM 32
#define BK 32
__global__ void gemm_kernel(const float* __restrict__ feat,
                            const float* __restrict__ W,
                            int N) {
    __shared__ float As[BK][BM];    // feat tile, transposed: As[k][r]
    __shared__ float Bs[BK][HD];    // W tile, transposed:   Bs[k][o]

    const int tid = threadIdx.x;          // 0..255
    const int cc  = tid & 31;             // col group 0..31  -> cols cc*4..cc*4+3
    const int rr  = tid >> 5;             // row group 0..7   -> rows rr*4..rr*4+3
    const int row0 = blockIdx.x * BM;

    float acc[4][4];
    #pragma unroll
    for (int i = 0; i < 4; i++)
        #pragma unroll
        for (int j = 0; j < 4; j++) acc[i][j] = 0.0f;

    for (int kc = 0; kc < IN_FEATS; kc += BK) {
        // Load feat tile: 32 rows x 32 k. One float4 per thread.
        {
            int r  = tid >> 3;            // 0..31
            int k4 = (tid & 7) << 2;      // 0,4,...,28
            float4 v = make_float4(0.f, 0.f, 0.f, 0.f);
            if (row0 + r < N)
                v = *(const float4*)&feat[(size_t)(row0 + r) * IN_FEATS + kc + k4];
            As[k4 + 0][r] = v.x; As[k4 + 1][r] = v.y;
            As[k4 + 2][r] = v.z; As[k4 + 3][r] = v.w;
        }
        // Load W tile: 128 o x 32 k. Four float4 per thread.
        #pragma unroll
        for (int it = 0; it < 4; it++) {
            int idx = tid + it * 256;     // 0..1023
            int o   = idx >> 3;           // 0..127
            int k4  = (idx & 7) << 2;
            float4 v = *(const float4*)&W[(size_t)o * IN_FEATS + kc + k4];
            Bs[k4 + 0][o] = v.x; Bs[k4 + 1][o] = v.y;
            Bs[k4 + 2][o] = v.z; Bs[k4 + 3][o] = v.w;
        }
        __syncthreads();

        #pragma unroll
        for (int k = 0; k < BK; k++) {
            float4 a = *(const float4*)&As[k][rr << 2];  // broadcast within warp
            float4 b = *(const float4*)&Bs[k][cc << 2];  // conflict-free LDS.128
            acc[0][0] += a.x * b.x; acc[0][1] += a.x * b.y; acc[0][2] += a.x * b.z; acc[0][3] += a.x * b.w;
            acc[1][0] += a.y * b.x; acc[1][1] += a.y * b.y; acc[1][2] += a.y * b.z; acc[1][3] += a.y * b.w;
            acc[2][0] += a.z * b.x; acc[2][1] += a.z * b.y; acc[2][2] += a.z * b.z; acc[2][3] += a.z * b.w;
            acc[3][0] += a.w * b.x; acc[3][1] += a.w * b.y; acc[3][2] += a.w * b.z; acc[3][3] += a.w * b.w;
        }
        __syncthreads();
    }

    #pragma unroll
    for (int i = 0; i < 4; i++) {
        int r = row0 + (rr << 2) + i;
        if (r < N) {
            float4 v = make_float4(acc[i][0], acc[i][1], acc[i][2], acc[i][3]);
            *(float4*)&g_ft[(size_t)r * HD + (cc << 2)] = v;
        }
    }
}

// ---------------------------------------------------------------------------
// K2: per-edge attention scores.
// Warp per edge. Lane l loads float4 l of ft[src] and ft[dst] (512B rows,
// fully coalesced, L2-resident). 8-lane shuffle reduction per head.
// e = exp(a * scale); atomicAdd into per-dst denominator.
// (Max-subtraction skipped: mathematically identical softmax; |a| <~ 7 so
// exp cannot overflow in fp32.)
// ---------------------------------------------------------------------------
__global__ void edge_score_kernel(const int* __restrict__ src,
                                  const int* __restrict__ dst,
                                  int E) {
    const int warp = (blockIdx.x * blockDim.x + threadIdx.x) >> 5;
    if (warp >= E) return;
    const int lane = threadIdx.x & 31;

    const int sn = src[warp];
    const int dn = dst[warp];

    const float4* ft4 = (const float4*)g_ft;   // 32 float4 per row
    float4 a4 = ft4[(size_t)sn * 32 + lane];
    float4 b4 = ft4[(size_t)dn * 32 + lane];
    float p = a4.x * b4.x + a4.y * b4.y + a4.z * b4.z + a4.w * b4.w;

    p += __shfl_xor_sync(0xffffffffu, p, 4);
    p += __shfl_xor_sync(0xffffffffu, p, 2);
    p += __shfl_xor_sync(0xffffffffu, p, 1);

    if ((lane & 7) == 0) {
        const int h = lane >> 3;
        const float scale = 0.17677669529663687f;  // 1/sqrt(32)
        float e = __expf(p * scale);
        g_e[(size_t)warp * NUM_HEADS + h] = e;
        atomicAdd(&g_s[(size_t)dn * NUM_HEADS + h], e);
    }
}

// ---------------------------------------------------------------------------
// K3: weighted scatter-aggregation.
// Warp per edge. w = e/s[dst]; out[dst] += ft[src] * w via float atomics.
// ---------------------------------------------------------------------------
__global__ void edge_aggregate_kernel(const int* __restrict__ src,
                                      const int* __restrict__ dst,
                                      float* __restrict__ out,
                                      int E) {
    const int warp = (blockIdx.x * blockDim.x + threadIdx.x) >> 5;
    if (warp >= E) return;
    const int lane = threadIdx.x & 31;
    const int h = lane >> 3;

    const int sn = src[warp];
    const int dn = dst[warp];

    const float e = g_e[(size_t)warp * NUM_HEADS + h];
    const float s = g_s[(size_t)dn * NUM_HEADS + h];
    const float w = e / s;

    const float4* ft4 = (const float4*)g_ft;
    float4 v = ft4[(size_t)sn * 32 + lane];

    float* o = out + (size_t)dn * HD + (lane << 2);
    atomicAdd(o + 0, v.x * w);
    atomicAdd(o + 1, v.y * w);
    atomicAdd(o + 2, v.z * w);
    atomicAdd(o + 3, v.w * w);
}

// ---------------------------------------------------------------------------
extern "C" void kernel_launch(void* const* d_in, const int* in_sizes, int n_in,
                              void* d_out, int out_size) {
    const float* feat = (const float*)d_in[0];
    const float* W    = (const float*)d_in[1];
    const int*   src  = (const int*)d_in[2];
    const int*   dst  = (const int*)d_in[3];
    float* out = (float*)d_out;

    const int N = in_sizes[0] / IN_FEATS;   // 50000
    const int E = in_sizes[2];              // 800000

    // Zero output + softmax denominators
    cudaMemsetAsync(out, 0, (size_t)out_size * sizeof(float));
    {
        int n = N * NUM_HEADS;
        zero_s_kernel<<<(n + 255) / 256, 256>>>(n);
    }

    // Projection GEMM
    gemm_kernel<<<(N + BM - 1) / BM, 256>>>(feat, W, N);

    // Edge scores + denominators
    {
        int warps_per_block = 8;  // 256 threads
        int blocks = (E + warps_per_block - 1) / warps_per_block;
        edge_score_kernel<<<blocks, 256>>>(src, dst, E);
    }

    // Weighted scatter-aggregate
    {
        int warps_per_block = 8;
        int blocks = (E + warps_per_block - 1) / warps_per_block;
        edge_aggregate_kernel<<<blocks, 256>>>(src, dst, out, E);
    }
}

// round 2
// speedup vs baseline: 2.0886x; 2.0886x over previous
#include <cuda_runtime.h>
#include <cuda_bf16.h>

// Problem constants (fixed by the dataset)
#define N_NODES_MAX 50000
#define N_EDGES_MAX 800000
#define IN_FEATS    128
#define NUM_HEADS   4
#define OUT_FEATS   32
#define HD          (NUM_HEADS * OUT_FEATS)   // 128

// Scratch (static __device__ arrays; no allocation allowed)
__device__ float g_ft[N_NODES_MAX * HD];          // projected features [N,128]
__device__ float g_s [N_NODES_MAX * NUM_HEADS];   // per-dst softmax denominators

// ---------------------------------------------------------------------------
// K0: zero the softmax denominators
// ---------------------------------------------------------------------------
__global__ void zero_s_kernel(int n) {
    int i = blockIdx.x * blockDim.x + threadIdx.x;
    if (i < n) g_s[i] = 0.0f;
}

// ---------------------------------------------------------------------------
// K1: ft[n][o] = sum_k feat[n][k] * W[o][k]
// Tiled SGEMM: BM=32 rows, BN=128 cols (all), BK=32. 256 threads, 4x4 microtile.
// ---------------------------------------------------------------------------
#define BM 32
#define BK 32
__global__ void gemm_kernel(const float* __restrict__ feat,
                            const float* __restrict__ W,
                            int N) {
    __shared__ float As[BK][BM];    // feat tile, transposed: As[k][r]
    __shared__ float Bs[BK][HD];    // W tile, transposed:   Bs[k][o]

    const int tid = threadIdx.x;          // 0..255
    const int cc  = tid & 31;             // col group 0..31  -> cols cc*4..cc*4+3
    const int rr  = tid >> 5;             // row group 0..7   -> rows rr*4..rr*4+3
    const int row0 = blockIdx.x * BM;

    float acc[4][4];
    #pragma unroll
    for (int i = 0; i < 4; i++)
        #pragma unroll
        for (int j = 0; j < 4; j++) acc[i][j] = 0.0f;

    for (int kc = 0; kc < IN_FEATS; kc += BK) {
        // Load feat tile: 32 rows x 32 k. One float4 per thread.
        {
            int r  = tid >> 3;            // 0..31
            int k4 = (tid & 7) << 2;      // 0,4,...,28
            float4 v = make_float4(0.f, 0.f, 0.f, 0.f);
            if (row0 + r < N)
                v = *(const float4*)&feat[(size_t)(row0 + r) * IN_FEATS + kc + k4];
            As[k4 + 0][r] = v.x; As[k4 + 1][r] = v.y;
            As[k4 + 2][r] = v.z; As[k4 + 3][r] = v.w;
        }
        // Load W tile: 128 o x 32 k. Four float4 per thread.
        #pragma unroll
        for (int it = 0; it < 4; it++) {
            int idx = tid + it * 256;     // 0..1023
            int o   = idx >> 3;           // 0..127
            int k4  = (idx & 7) << 2;
            float4 v = *(const float4*)&W[(size_t)o * IN_FEATS + kc + k4];
            Bs[k4 + 0][o] = v.x; Bs[k4 + 1][o] = v.y;
            Bs[k4 + 2][o] = v.z; Bs[k4 + 3][o] = v.w;
        }
        __syncthreads();

        #pragma unroll
        for (int k = 0; k < BK; k++) {
            float4 a = *(const float4*)&As[k][rr << 2];
            float4 b = *(const float4*)&Bs[k][cc << 2];
            acc[0][0] += a.x * b.x; acc[0][1] += a.x * b.y; acc[0][2] += a.x * b.z; acc[0][3] += a.x * b.w;
            acc[1][0] += a.y * b.x; acc[1][1] += a.y * b.y; acc[1][2] += a.y * b.z; acc[1][3] += a.y * b.w;
            acc[2][0] += a.z * b.x; acc[2][1] += a.z * b.y; acc[2][2] += a.z * b.z; acc[2][3] += a.z * b.w;
            acc[3][0] += a.w * b.x; acc[3][1] += a.w * b.y; acc[3][2] += a.w * b.z; acc[3][3] += a.w * b.w;
        }
        __syncthreads();
    }

    #pragma unroll
    for (int i = 0; i < 4; i++) {
        int r = row0 + (rr << 2) + i;
        if (r < N) {
            float4 v = make_float4(acc[i][0], acc[i][1], acc[i][2], acc[i][3]);
            *(float4*)&g_ft[(size_t)r * HD + (cc << 2)] = v;
        }
    }
}

// ---------------------------------------------------------------------------
// K2: FUSED edge pass.
// Warp per edge. Lane l loads float4 l of ft[src] and ft[dst] (512B rows,
// fully coalesced, L2-resident). Per-head dot via 8-lane shuffle reduction;
// after xor-4/2/1 all 8 lanes of a head hold the full partial sum.
// e = exp(a*scale). One lane per head adds e into the dst denominator;
// ALL lanes scatter e * ft[src] into out[dst] with a single vector RED
// (red.global.add.v4.f32 — 4x fewer LTS atomic transactions than scalar).
// Normalization by s is deferred to K3 (division distributes over the sum).
// Max-subtraction skipped: mathematically identical softmax; |a| <~ 7 so
// exp cannot overflow fp32.
// ---------------------------------------------------------------------------
__global__ void edge_fused_kernel(const int* __restrict__ src,
                                  const int* __restrict__ dst,
                                  float* __restrict__ out,
                                  int E) {
    const int warp = (blockIdx.x * blockDim.x + threadIdx.x) >> 5;
    if (warp >= E) return;
    const int lane = threadIdx.x & 31;
    const int h = lane >> 3;

    const int sn = src[warp];
    const int dn = dst[warp];

    const float4* ft4 = (const float4*)g_ft;   // 32 float4 per row
    float4 a4 = ft4[(size_t)sn * 32 + lane];   // ft[src] chunk (reused for scatter)
    float4 b4 = ft4[(size_t)dn * 32 + lane];   // ft[dst] chunk
    float p = a4.x * b4.x + a4.y * b4.y + a4.z * b4.z + a4.w * b4.w;

    p += __shfl_xor_sync(0xffffffffu, p, 4);
    p += __shfl_xor_sync(0xffffffffu, p, 2);
    p += __shfl_xor_sync(0xffffffffu, p, 1);
    // now every lane in each 8-lane head group holds the head's dot product

    const float scale = 0.17677669529663687f;  // 1/sqrt(32)
    const float e = __expf(p * scale);

    if ((lane & 7) == 0)
        atomicAdd(&g_s[(size_t)dn * NUM_HEADS + h], e);

    float* o = out + (size_t)dn * HD + (lane << 2);
    asm volatile("red.global.add.v4.f32 [%0], {%1, %2, %3, %4};"
                 :: "l"(o), "f"(a4.x * e), "f"(a4.y * e),
                    "f"(a4.z * e), "f"(a4.w * e)
                 : "memory");
}

// ---------------------------------------------------------------------------
// K3: normalize. out[n][h][:] /= s[n][h]. One float4 per thread.
// ---------------------------------------------------------------------------
__global__ void normalize_kernel(float* __restrict__ out, int N) {
    int i4 = blockIdx.x * blockDim.x + threadIdx.x;   // index into float4 view
    if (i4 >= N * 32) return;
    int n = i4 >> 5;
    int h = (i4 >> 3) & 3;
    float inv = 1.0f / g_s[(size_t)n * NUM_HEADS + h];
    float4* o4 = (float4*)out;
    float4 v = o4[i4];
    v.x *= inv; v.y *= inv; v.z *= inv; v.w *= inv;
    o4[i4] = v;
}

// ---------------------------------------------------------------------------
extern "C" void kernel_launch(void* const* d_in, const int* in_sizes, int n_in,
                              void* d_out, int out_size) {
    const float* feat = (const float*)d_in[0];
    const float* W    = (const float*)d_in[1];
    const int*   src  = (const int*)d_in[2];
    const int*   dst  = (const int*)d_in[3];
    float* out = (float*)d_out;

    const int N = in_sizes[0] / IN_FEATS;   // 50000
    const int E = in_sizes[2];              // 800000

    // Zero output + softmax denominators
    cudaMemsetAsync(out, 0, (size_t)out_size * sizeof(float));
    {
        int n = N * NUM_HEADS;
        zero_s_kernel<<<(n + 255) / 256, 256>>>(n);
    }

    // Projection GEMM
    gemm_kernel<<<(N + BM - 1) / BM, 256>>>(feat, W, N);

    // Fused edge pass: scores + denominators + unnormalized scatter
    {
        int warps_per_block = 8;  // 256 threads
        int blocks = (E + warps_per_block - 1) / warps_per_block;
        edge_fused_kernel<<<blocks, 256>>>(src, dst, out, E);
    }

    // Normalize by per-(dst, head) softmax denominator
    {
        int n4 = N * 32;
        normalize_kernel<<<(n4 + 255) / 256, 256>>>(out, N);
    }
}

// round 3
// speedup vs baseline: 2.7537x; 1.3185x over previous
#include <cuda_runtime.h>
#include <cuda_bf16.h>

// Problem constants (fixed by the dataset)
#define N_NODES_MAX 50048
#define N_EDGES_MAX 800000
#define IN_FEATS    128
#define NUM_HEADS   4
#define OUT_FEATS   32
#define HD          (NUM_HEADS * OUT_FEATS)   // 128

#define SCAN_B 1024
#define MAX_BLOCKS ((N_NODES_MAX + SCAN_B - 1) / SCAN_B + 2)

// Scratch (static __device__ arrays; no allocation allowed)
__device__ float g_ft[N_NODES_MAX * HD];     // projected features [N,128]
__device__ int   g_cnt[N_NODES_MAX];         // in-degree histogram
__device__ int   g_off[N_NODES_MAX];         // CSR row starts (exclusive scan)
__device__ int   g_cur[N_NODES_MAX];         // scatter cursors
__device__ int   g_bsum[MAX_BLOCKS];         // block partial sums for scan
__device__ int   g_csr_src[N_EDGES_MAX];     // src node per CSR slot

// ---------------------------------------------------------------------------
// K0: zero the degree histogram
// ---------------------------------------------------------------------------
__global__ void zero_cnt_kernel(int n) {
    int i = blockIdx.x * blockDim.x + threadIdx.x;
    if (i < n) g_cnt[i] = 0;
}

// ---------------------------------------------------------------------------
// K1: in-degree histogram
// ---------------------------------------------------------------------------
__global__ void hist_kernel(const int* __restrict__ dst, int E) {
    int i = blockIdx.x * blockDim.x + threadIdx.x;
    if (i < E) atomicAdd(&g_cnt[dst[i]], 1);
}

// ---------------------------------------------------------------------------
// K2a/K2b/K2c: 3-phase exclusive scan over g_cnt -> g_off (+ g_cur copy)
// ---------------------------------------------------------------------------
__global__ void scan_phase1(int N) {
    int i = blockIdx.x * SCAN_B + threadIdx.x;
    int v = (i < N) ? g_cnt[i] : 0;
    // warp reduce
    #pragma unroll
    for (int o = 16; o > 0; o >>= 1) v += __shfl_xor_sync(0xffffffffu, v, o);
    __shared__ int wsum[32];
    int lane = threadIdx.x & 31, w = threadIdx.x >> 5;
    if (lane == 0) wsum[w] = v;
    __syncthreads();
    if (w == 0) {
        int x = wsum[lane];
        #pragma unroll
        for (int o = 16; o > 0; o >>= 1) x += __shfl_xor_sync(0xffffffffu, x, o);
        if (lane == 0) g_bsum[blockIdx.x] = x;
    }
}

__global__ void scan_phase2(int nb) {
    // single block of 64 threads; Hillis-Steele inclusive, convert to exclusive
    __shared__ int sh[64];
    int t = threadIdx.x;
    int v = (t < nb) ? g_bsum[t] : 0;
    sh[t] = v;
    __syncthreads();
    #pragma unroll
    for (int o = 1; o < 64; o <<= 1) {
        int x = (t >= o) ? sh[t - o] : 0;
        __syncthreads();
        sh[t] += x;
        __syncthreads();
    }
    if (t < nb) g_bsum[t] = sh[t] - v;   // exclusive
}

__global__ void scan_phase3(int N) {
    int i = blockIdx.x * SCAN_B + threadIdx.x;
    int v = (i < N) ? g_cnt[i] : 0;
    int lane = threadIdx.x & 31, w = threadIdx.x >> 5;
    // warp inclusive scan
    int x = v;
    #pragma unroll
    for (int o = 1; o < 32; o <<= 1) {
        int y = __shfl_up_sync(0xffffffffu, x, o);
        if (lane >= o) x += y;
    }
    __shared__ int woff[32];
    if (lane == 31) woff[w] = x;
    __syncthreads();
    if (w == 0) {
        int y = woff[lane];
        int z = y;
        #pragma unroll
        for (int o = 1; o < 32; o <<= 1) {
            int t2 = __shfl_up_sync(0xffffffffu, z, o);
            if (lane >= o) z += t2;
        }
        woff[lane] = z - y;   // exclusive warp offsets
    }
    __syncthreads();
    int excl = (x - v) + woff[w] + g_bsum[blockIdx.x];
    if (i < N) { g_off[i] = excl; g_cur[i] = excl; }
}

// ---------------------------------------------------------------------------
// K3: scatter src ids into CSR slots
// ---------------------------------------------------------------------------
__global__ void scatter_kernel(const int* __restrict__ src,
                               const int* __restrict__ dst, int E) {
    int i = blockIdx.x * blockDim.x + threadIdx.x;
    if (i < E) {
        int pos = atomicAdd(&g_cur[dst[i]], 1);
        g_csr_src[pos] = src[i];
    }
}

// ---------------------------------------------------------------------------
// K4: projection GEMM. ft[n][o] = sum_k feat[n][k] * W[o][k]
// Tiled SGEMM: BM=32 rows, BN=128 cols (all), BK=32. 256 threads, 4x4 microtile.
// ---------------------------------------------------------------------------
#define BM 32
#define BK 32
__global__ void gemm_kernel(const float* __restrict__ feat,
                            const float* __restrict__ W,
                            int N) {
    __shared__ float As[BK][BM];    // feat tile, transposed: As[k][r]
    __shared__ float Bs[BK][HD];    // W tile, transposed:   Bs[k][o]

    const int tid = threadIdx.x;          // 0..255
    const int cc  = tid & 31;
    const int rr  = tid >> 5;
    const int row0 = blockIdx.x * BM;

    float acc[4][4];
    #pragma unroll
    for (int i = 0; i < 4; i++)
        #pragma unroll
        for (int j = 0; j < 4; j++) acc[i][j] = 0.0f;

    for (int kc = 0; kc < IN_FEATS; kc += BK) {
        {
            int r  = tid >> 3;
            int k4 = (tid & 7) << 2;
            float4 v = make_float4(0.f, 0.f, 0.f, 0.f);
            if (row0 + r < N)
                v = *(const float4*)&feat[(size_t)(row0 + r) * IN_FEATS + kc + k4];
            As[k4 + 0][r] = v.x; As[k4 + 1][r] = v.y;
            As[k4 + 2][r] = v.z; As[k4 + 3][r] = v.w;
        }
        #pragma unroll
        for (int it = 0; it < 4; it++) {
            int idx = tid + it * 256;
            int o   = idx >> 3;
            int k4  = (idx & 7) << 2;
            float4 v = *(const float4*)&W[(size_t)o * IN_FEATS + kc + k4];
            Bs[k4 + 0][o] = v.x; Bs[k4 + 1][o] = v.y;
            Bs[k4 + 2][o] = v.z; Bs[k4 + 3][o] = v.w;
        }
        __syncthreads();

        #pragma unroll
        for (int k = 0; k < BK; k++) {
            float4 a = *(const float4*)&As[k][rr << 2];
            float4 b = *(const float4*)&Bs[k][cc << 2];
            acc[0][0] += a.x * b.x; acc[0][1] += a.x * b.y; acc[0][2] += a.x * b.z; acc[0][3] += a.x * b.w;
            acc[1][0] += a.y * b.x; acc[1][1] += a.y * b.y; acc[1][2] += a.y * b.z; acc[1][3] += a.y * b.w;
            acc[2][0] += a.z * b.x; acc[2][1] += a.z * b.y; acc[2][2] += a.z * b.z; acc[2][3] += a.z * b.w;
            acc[3][0] += a.w * b.x; acc[3][1] += a.w * b.y; acc[3][2] += a.w * b.z; acc[3][3] += a.w * b.w;
        }
        __syncthreads();
    }

    #pragma unroll
    for (int i = 0; i < 4; i++) {
        int r = row0 + (rr << 2) + i;
        if (r < N) {
            float4 v = make_float4(acc[i][0], acc[i][1], acc[i][2], acc[i][3]);
            *(float4*)&g_ft[(size_t)r * HD + (cc << 2)] = v;
        }
    }
}

// ---------------------------------------------------------------------------
// K5: atomic-free aggregation. One warp per DST node.
// ft[dst] held in registers (1 float4/lane). For each in-edge: coalesced
// csr_src read (32 at a time, shuffled out), gather ft[src] row, per-head
// dot via 8-lane xor-shuffle (all lanes of a head end with the same p),
// e = exp(p*scale); accumulate e*ft[src] and denominator s in registers.
// Final write: acc/s, one float4 per lane. No atomics anywhere.
// Max-subtraction skipped: mathematically identical softmax; |p*scale| <~ 7.
// ---------------------------------------------------------------------------
__global__ void agg_kernel(float* __restrict__ out, int N) {
    const int node = (blockIdx.x * blockDim.x + threadIdx.x) >> 5;
    if (node >= N) return;
    const int lane = threadIdx.x & 31;

    const int start = g_off[node];
    const int deg   = g_cnt[node];

    const float4* ft4 = (const float4*)g_ft;
    const float4 b4 = ft4[(size_t)node * 32 + lane];

    float4 acc = make_float4(0.f, 0.f, 0.f, 0.f);
    float s = 0.0f;
    const float scale = 0.17677669529663687f;  // 1/sqrt(32)

    for (int base = 0; base < deg; base += 32) {
        int j = base + lane;
        int sj = (j < deg) ? g_csr_src[start + j] : 0;
        int cnt = min(32, deg - base);
        #pragma unroll 2
        for (int t = 0; t < cnt; t++) {
            int sn = __shfl_sync(0xffffffffu, sj, t);
            float4 a4 = ft4[(size_t)sn * 32 + lane];
            float p = a4.x * b4.x + a4.y * b4.y + a4.z * b4.z + a4.w * b4.w;
            p += __shfl_xor_sync(0xffffffffu, p, 4);
            p += __shfl_xor_sync(0xffffffffu, p, 2);
            p += __shfl_xor_sync(0xffffffffu, p, 1);
            float e = __expf(p * scale);
            s += e;
            acc.x += e * a4.x; acc.y += e * a4.y;
            acc.z += e * a4.z; acc.w += e * a4.w;
        }
    }

    float inv = (deg > 0) ? (1.0f / s) : 0.0f;
    float4 r = make_float4(acc.x * inv, acc.y * inv, acc.z * inv, acc.w * inv);
    ((float4*)out)[(size_t)node * 32 + lane] = r;
}

// ---------------------------------------------------------------------------
extern "C" void kernel_launch(void* const* d_in, const int* in_sizes, int n_in,
                              void* d_out, int out_size) {
    const float* feat = (const float*)d_in[0];
    const float* W    = (const float*)d_in[1];
    const int*   src  = (const int*)d_in[2];
    const int*   dst  = (const int*)d_in[3];
    float* out = (float*)d_out;

    const int N = in_sizes[0] / IN_FEATS;   // 50000
    const int E = in_sizes[2];              // 800000

    const int nb = (N + SCAN_B - 1) / SCAN_B;

    // CSR build
    zero_cnt_kernel<<<(N + 255) / 256, 256>>>(N);
    hist_kernel<<<(E + 255) / 256, 256>>>(dst, E);
    scan_phase1<<<nb, SCAN_B>>>(N);
    scan_phase2<<<1, 64>>>(nb);
    scan_phase3<<<nb, SCAN_B>>>(N);
    scatter_kernel<<<(E + 255) / 256, 256>>>(src, dst, E);

    // Projection GEMM
    gemm_kernel<<<(N + BM - 1) / BM, 256>>>(feat, W, N);

    // Atomic-free aggregation (warp per dst node)
    {
        int warps_per_block = 8;  // 256 threads
        int blocks = (N + warps_per_block - 1) / warps_per_block;
        agg_kernel<<<blocks, 256>>>(out, N);
    }
}